// round 7
// baseline (speedup 1.0000x reference)
#include <cuda_runtime.h>
#include <cstdint>
#include <math.h>

// Problem constants: N=8, S=8192, C=1, K=1024, V=64
#define NS_TOTAL 65536
#define VDIM 64
#define KCW 1024
#define BM 128
#define THREADS 512
#define EPS 6.0e-3f

// ---- smem layout (bytes) ----
#define SM_EQ    0        // uint eq[16][1024] packed int8 e (65536)
#define SM_XQ    65536    // uint xq[16][128] packed int8 x (8192)
#define SM_XF    73728    // fp32 xf[128][65] padded (33280)
#define SM_EN    107008   // fp32 [1024] (4096)
#define SM_SE    111104   // fp32 [1024] e scales (4096)
#define SM_XN    115200   // fp32 [128] (512)
#define SM_C2X   115712   // fp32 [128] 2*s_x (512)
#define SM_CNT   116224   // int  [128] (512)
#define SM_CAND  116736   // u16  [128][16] (4096)
#define SM_AMIN  120832   // int  [128] (512)
#define SM_RSUM  121344   // fp32 [128] (512)
#define SMEM_BYTES 121856

typedef unsigned int uint;

__device__ float g_en[KCW];
__device__ float g_se[KCW];
__device__ uint  g_eq[16 * KCW];     // [v4][k] packed int8 codebook
__device__ int   g_counts[KCW];
__device__ int   g_nflag;
__device__ int   g_flagrows[NS_TOTAL];

__device__ __forceinline__ uint pack_q4(float f0, float f1, float f2, float f3, float inv) {
    int q0 = __float2int_rn(f0 * inv);
    int q1 = __float2int_rn(f1 * inv);
    int q2 = __float2int_rn(f2 * inv);
    int q3 = __float2int_rn(f3 * inv);
    return (uint)(q0 & 0xff) | ((uint)(q1 & 0xff) << 8) |
           ((uint)(q2 & 0xff) << 16) | ((uint)(q3 & 0xff) << 24);
}

// ---------------------------------------------------------------------------
// Kernel 1: prep — exact en (sequential mul+add), e scale + packed int8 e,
// zero histogram/flags. 1024 threads, one per codeword.
// ---------------------------------------------------------------------------
__global__ void vq_prep_kernel(const float* __restrict__ emb) {
    int k = blockIdx.x * blockDim.x + threadIdx.x;
    if (k >= KCW) return;
    const float* e = emb + (size_t)k * VDIM;
    float acc = 0.0f, mx = 0.0f;
    #pragma unroll 8
    for (int v = 0; v < VDIM; v++) {
        float ev = e[v];
        acc = __fadd_rn(acc, __fmul_rn(ev, ev));
        mx = fmaxf(mx, fabsf(ev));
    }
    float se  = mx * (1.0f / 127.0f);
    float inv = (mx > 0.0f) ? 127.0f / mx : 0.0f;
    g_en[k] = acc;
    g_se[k] = se;
    g_counts[k] = 0;
    if (k == 0) g_nflag = 0;
    #pragma unroll
    for (int v4 = 0; v4 < 16; v4++)
        g_eq[v4 * KCW + k] = pack_q4(e[4*v4], e[4*v4+1], e[4*v4+2], e[4*v4+3], inv);
}

// ---------------------------------------------------------------------------
// Kernel 2: int8 dp4a filter GEMM (single sweep, streaming threshold) +
// exact rescore + outputs. grid 512 x 512 threads, 1 CTA/SM.
// thread tile: 8 rows x 8 codewords; warp owns rows [ty*8, ty*8+8).
// ---------------------------------------------------------------------------
__global__ __launch_bounds__(THREADS, 1)
void vq_dp4a_kernel(const float* __restrict__ x, const float* __restrict__ emb,
                    float* __restrict__ out0, float* __restrict__ out1,
                    float* __restrict__ out2) {
    extern __shared__ char sm[];
    uint*  eq     = (uint*)(sm + SM_EQ);
    uint*  xq     = (uint*)(sm + SM_XQ);
    float* xf     = (float*)(sm + SM_XF);
    float* en_s   = (float*)(sm + SM_EN);
    float* se_s   = (float*)(sm + SM_SE);
    float* xn_s   = (float*)(sm + SM_XN);
    float* c2x_s  = (float*)(sm + SM_C2X);
    int*   rowcnt = (int*)(sm + SM_CNT);
    unsigned short* cand = (unsigned short*)(sm + SM_CAND);
    int*   amin_s = (int*)(sm + SM_AMIN);
    float* rsum   = (float*)(sm + SM_RSUM);

    const int tid = threadIdx.x;
    const int tx  = tid & 31;            // codeword group: 8 cw at c*256 + tx*8
    const int ty  = tid >> 5;            // row group: rows ty*8 .. ty*8+7
    const int row0 = blockIdx.x * BM;

    // ---- load x tile into fp32 smem (coalesced float4) ----
    const float4* x4 = reinterpret_cast<const float4*>(x) + (size_t)row0 * (VDIM / 4);
    #pragma unroll
    for (int t = 0; t < 4; t++) {
        int idx = tid + t * THREADS;     // 2048 float4
        int r   = idx >> 4;
        int v4  = idx & 15;
        float4 f = x4[idx];
        float* d = xf + r * 65 + v4 * 4;
        d[0] = f.x; d[1] = f.y; d[2] = f.z; d[3] = f.w;
    }
    // ---- load E tables: packed int8 (65536 B) + en + se ----
    {
        const uint4* src = reinterpret_cast<const uint4*>(g_eq);
        uint4* dst = reinterpret_cast<uint4*>(eq);
        #pragma unroll
        for (int t = 0; t < 8; t++) dst[tid + t * THREADS] = src[tid + t * THREADS];
        #pragma unroll
        for (int t = 0; t < 2; t++) {
            en_s[tid + t * THREADS] = g_en[tid + t * THREADS];
            se_s[tid + t * THREADS] = g_se[tid + t * THREADS];
        }
    }
    if (tid < BM) { rowcnt[tid] = 0; rsum[tid] = 0.0f; }
    __syncthreads();

    // ---- per-row: exact xn (sequential mul+add), scale, quantize+pack x ----
    if (tid < BM) {
        const float* xr = xf + tid * 65;
        float acc = 0.0f, mx = 0.0f;
        #pragma unroll 8
        for (int v = 0; v < VDIM; v++) {
            float xv = xr[v];
            acc = __fadd_rn(acc, __fmul_rn(xv, xv));
            mx = fmaxf(mx, fabsf(xv));
        }
        xn_s[tid]  = acc;
        c2x_s[tid] = 2.0f * mx * (1.0f / 127.0f);
        float inv = (mx > 0.0f) ? 127.0f / mx : 0.0f;
        #pragma unroll
        for (int v4 = 0; v4 < 16; v4++)
            xq[v4 * 128 + tid] = pack_q4(xr[4*v4], xr[4*v4+1], xr[4*v4+2], xr[4*v4+3], inv);
    }
    __syncthreads();

    // =================== single-sweep int8 filter over 4 chunks ===================
    float rowmin[8];
    #pragma unroll
    for (int i = 0; i < 8; i++) rowmin[i] = 3.402823466e38f;

    #pragma unroll 1
    for (int c = 0; c < 4; c++) {
        int acc[8][8];
        #pragma unroll
        for (int i = 0; i < 8; i++)
            #pragma unroll
            for (int m = 0; m < 8; m++) acc[i][m] = 0;

        const uint* ebp = eq + c * 256 + tx * 8;
        const uint* xbp = xq + ty * 8;
        #pragma unroll
        for (int v4 = 0; v4 < 16; v4++) {
            uint4 e01 = *reinterpret_cast<const uint4*>(ebp + v4 * KCW);
            uint4 e23 = *reinterpret_cast<const uint4*>(ebp + v4 * KCW + 4);
            uint4 x01 = *reinterpret_cast<const uint4*>(xbp + v4 * 128);
            uint4 x23 = *reinterpret_cast<const uint4*>(xbp + v4 * 128 + 4);
            uint ev[8] = {e01.x, e01.y, e01.z, e01.w, e23.x, e23.y, e23.z, e23.w};
            uint xv[8] = {x01.x, x01.y, x01.z, x01.w, x23.x, x23.y, x23.z, x23.w};
            #pragma unroll
            for (int i = 0; i < 8; i++)
                #pragma unroll
                for (int m = 0; m < 8; m++)
                    acc[i][m] = __dp4a((int)xv[i], (int)ev[m], acc[i][m]);
        }

        // epilogue: u = en - (2*s_x*s_e)*idot ; streaming row-min + collect
        float se[8], enl[8];
        const int kb = c * 256 + tx * 8;
        #pragma unroll
        for (int m = 0; m < 8; m++) { se[m] = se_s[kb + m]; enl[m] = en_s[kb + m]; }
        #pragma unroll
        for (int i = 0; i < 8; i++) {
            int r = ty * 8 + i;
            float c2 = c2x_s[r];
            float u[8];
            float cmin = 3.402823466e38f;
            #pragma unroll
            for (int m = 0; m < 8; m++) {
                u[m] = __fmaf_rn(-(c2 * se[m]), (float)acc[i][m], enl[m]);
                cmin = fminf(cmin, u[m]);
            }
            cmin = fminf(cmin, __shfl_xor_sync(0xffffffffu, cmin, 1));
            cmin = fminf(cmin, __shfl_xor_sync(0xffffffffu, cmin, 2));
            cmin = fminf(cmin, __shfl_xor_sync(0xffffffffu, cmin, 4));
            cmin = fminf(cmin, __shfl_xor_sync(0xffffffffu, cmin, 8));
            cmin = fminf(cmin, __shfl_xor_sync(0xffffffffu, cmin, 16));
            rowmin[i] = fminf(rowmin[i], cmin);
            float thr = rowmin[i] + EPS;
            #pragma unroll
            for (int m = 0; m < 8; m++) {
                if (u[m] <= thr) {
                    int p = atomicAdd(&rowcnt[r], 1);
                    if (p < 16) cand[r * 16 + p] = (unsigned short)(kb + m);
                }
            }
        }
    }
    __syncthreads();

    // ---- exact rescore (thread-per-row, reference rounding, lexicographic) ----
    if (tid < BM) {
        int cnt = rowcnt[tid];
        if (cnt <= 16) {
            float bv = 3.402823466e38f;
            int   bi = 1 << 30;
            const float* xr = xf + tid * 65;
            float xn = xn_s[tid];
            for (int cI = 0; cI < cnt; cI++) {
                int k = cand[tid * 16 + cI];
                const float* er = emb + (size_t)k * VDIM;
                float acc = 0.0f;
                #pragma unroll 16
                for (int v = 0; v < VDIM; v++)
                    acc = __fmaf_rn(xr[v], er[v], acc);
                float s = __fadd_rn(__fsub_rn(xn, __fmul_rn(2.0f, acc)), en_s[k]);
                if (s < bv || (s == bv && k < bi)) { bv = s; bi = k; }
            }
            amin_s[tid] = bi;
            atomicAdd(&g_counts[bi], 1);
        } else {
            int pos = atomicAdd(&g_nflag, 1);
            g_flagrows[pos] = row0 + tid;
            amin_s[tid] = -1;
        }
    }
    __syncthreads();

    // ---- outputs: out0 = fl(fl(o-x)+x); out1 = out2 = sum (x-o)^2 ----
    #pragma unroll 4
    for (int t = 0; t < 16; t++) {
        int i = t * THREADS + tid;       // 8192 elements; warp = half a row
        int r = i >> 6;
        int v = i & 63;
        int bi = amin_s[r];
        if (bi >= 0) {
            float o  = emb[(size_t)bi * VDIM + v];
            float xv = xf[r * 65 + v];
            float dd = __fsub_rn(xv, o);
            float sq = __fmul_rn(dd, dd);
            #pragma unroll
            for (int off = 16; off > 0; off >>= 1)
                sq += __shfl_down_sync(0xffffffffu, sq, off);
            if ((tid & 31) == 0) atomicAdd(&rsum[r], sq);   // 2 adds/row: order-invariant
            out0[(size_t)(row0 + r) * VDIM + v] = __fadd_rn(__fsub_rn(o, xv), xv);
        }
    }
    __syncthreads();
    if (tid < BM && amin_s[tid] >= 0) {
        float s = rsum[tid];
        out1[row0 + tid] = s;
        out2[row0 + tid] = s;
    }
}

// ---------------------------------------------------------------------------
// Kernel 3: fallback for shortlist-overflow rows (full exact 1024-scan)
// ---------------------------------------------------------------------------
__global__ void vq_fix_kernel(const float* __restrict__ x, const float* __restrict__ emb,
                              float* __restrict__ out0, float* __restrict__ out1,
                              float* __restrict__ out2) {
    __shared__ float xrow[8][65];
    int nf  = g_nflag;
    int wid = threadIdx.x >> 5;
    int lid = threadIdx.x & 31;
    for (int f = blockIdx.x * 8 + wid; f < nf; f += gridDim.x * 8) {
        int row = g_flagrows[f];
        const float* xr = x + (size_t)row * VDIM;
        xrow[wid][lid]      = xr[lid];
        xrow[wid][lid + 32] = xr[lid + 32];
        __syncwarp();
        float xn = 0.0f;
        #pragma unroll 8
        for (int v = 0; v < VDIM; v++)
            xn = __fadd_rn(xn, __fmul_rn(xrow[wid][v], xrow[wid][v]));
        float bv = 3.402823466e38f;
        int   bi = 1 << 30;
        for (int j = 0; j < 32; j++) {
            int k = j * 32 + lid;
            const float* er = emb + (size_t)k * VDIM;
            float acc = 0.0f;
            #pragma unroll 16
            for (int v = 0; v < VDIM; v++)
                acc = __fmaf_rn(xrow[wid][v], er[v], acc);
            float s = __fadd_rn(__fsub_rn(xn, __fmul_rn(2.0f, acc)), g_en[k]);
            if (s < bv || (s == bv && k < bi)) { bv = s; bi = k; }
        }
        #pragma unroll
        for (int off = 16; off > 0; off >>= 1) {
            float ov = __shfl_down_sync(0xffffffffu, bv, off);
            int   oi = __shfl_down_sync(0xffffffffu, bi, off);
            if (ov < bv || (ov == bv && oi < bi)) { bv = ov; bi = oi; }
        }
        bi = __shfl_sync(0xffffffffu, bi, 0);
        if (lid == 0) atomicAdd(&g_counts[bi], 1);
        float sq = 0.0f;
        #pragma unroll
        for (int h = 0; h < 2; h++) {
            int v = lid + 32 * h;
            float o  = emb[(size_t)bi * VDIM + v];
            float xv = xrow[wid][v];
            float dd = __fsub_rn(xv, o);
            sq += dd * dd;
            out0[(size_t)row * VDIM + v] = __fadd_rn(__fsub_rn(o, xv), xv);
        }
        #pragma unroll
        for (int off = 16; off > 0; off >>= 1)
            sq += __shfl_down_sync(0xffffffffu, sq, off);
        if (lid == 0) { out1[row] = sq; out2[row] = sq; }
        __syncwarp();
    }
}

// ---------------------------------------------------------------------------
// Kernel 4: entropy of the histogram
// ---------------------------------------------------------------------------
__global__ void vq_entropy_kernel(float* __restrict__ ent) {
    __shared__ float warpsum[32];
    int k = threadIdx.x;
    int c = g_counts[k];
    float term = 0.0f;
    if (c > 0) {
        float p = (float)c * (1.0f / 65536.0f);
        term = -p * logf(p);
    }
    #pragma unroll
    for (int off = 16; off > 0; off >>= 1)
        term += __shfl_down_sync(0xffffffffu, term, off);
    int lane = k & 31, wid = k >> 5;
    if (lane == 0) warpsum[wid] = term;
    __syncthreads();
    if (wid == 0) {
        float s = warpsum[lane];
        #pragma unroll
        for (int off = 16; off > 0; off >>= 1)
            s += __shfl_down_sync(0xffffffffu, s, off);
        if (lane == 0) *ent = s;
    }
}

// ---------------------------------------------------------------------------
extern "C" void kernel_launch(void* const* d_in, const int* in_sizes, int n_in,
                              void* d_out, int out_size) {
    const float* x;
    const float* emb;
    if (in_sizes[0] == NS_TOTAL * VDIM) {
        x   = (const float*)d_in[0];
        emb = (const float*)d_in[1];
    } else {
        x   = (const float*)d_in[1];
        emb = (const float*)d_in[0];
    }

    float* out0 = (float*)d_out;
    float* out1 = out0 + (size_t)NS_TOTAL * VDIM;
    float* out2 = out1 + NS_TOTAL;
    float* ent  = out2 + NS_TOTAL;

    cudaFuncSetAttribute(vq_dp4a_kernel,
                         cudaFuncAttributeMaxDynamicSharedMemorySize, SMEM_BYTES);

    vq_prep_kernel<<<4, 256>>>(emb);
    vq_dp4a_kernel<<<512, THREADS, SMEM_BYTES>>>(x, emb, out0, out1, out2);
    vq_fix_kernel<<<32, 256>>>(x, emb, out0, out1, out2);
    vq_entropy_kernel<<<1, 1024>>>(ent);
}

// round 8
// speedup vs baseline: 5.5976x; 5.5976x over previous
#include <cuda_runtime.h>
#include <math.h>

// Problem constants: N=8, S=8192, C=1, K=1024, V=64
#define NS_TOTAL 65536
#define VDIM 64
#define KCW 1024
#define BM 64                  // rows per CTA (grid 1024 -> 6.92 tiles/SM, 98.9% wave eff)
#define BK 256
#define NCHUNK (KCW / BK)      // 4

#define XST 130                // x stride: 2*BM + 2
#define EST 258                // e stride: BK + 2
#define XS_FLOATS (VDIM * XST) // 8320
#define ES_FLOATS (VDIM * EST) // 16512
#define SMEM_BYTES 120000      // padded: 2 CTAs would need 240000 > 227KB -> forces 1 CTA/SM

typedef unsigned long long ull;

__device__ float g_en[KCW];
__device__ int   g_counts[KCW];

// Packed fp32x2 ops (split to scalar FFMA by ptxas on this target, but IEEE-rn
// per lane either way — keeps the proven bit-exact accumulation order).
__device__ __forceinline__ ull ffma2(ull a, ull b, ull c) {
    ull d;
    asm("fma.rn.f32x2 %0, %1, %2, %3;" : "=l"(d) : "l"(a), "l"(b), "l"(c));
    return d;
}
__device__ __forceinline__ ull fmul2(ull a, ull b) {
    ull d;
    asm("mul.rn.f32x2 %0, %1, %2;" : "=l"(d) : "l"(a), "l"(b));
    return d;
}
__device__ __forceinline__ ull fadd2(ull a, ull b) {
    ull d;
    asm("add.rn.f32x2 %0, %1, %2;" : "=l"(d) : "l"(a), "l"(b));
    return d;
}
__device__ __forceinline__ void unpack2(ull v, float& lo, float& hi) {
    unsigned int l, h;
    asm("mov.b64 {%0, %1}, %2;" : "=r"(l), "=r"(h) : "l"(v));
    lo = __uint_as_float(l);
    hi = __uint_as_float(h);
}
__device__ __forceinline__ ull pack2(float lo, float hi) {
    ull v;
    asm("mov.b64 %0, {%1, %2};" : "=l"(v) : "f"(lo), "f"(hi));
    return v;
}

// e-tile bank swizzle: float-index idx -> idx ^ (4*((v>>2)&7)).
// Touches float-idx bits [2..4] only: keeps ull pair adjacency/alignment and
// commutes with +32*m (bit5+). Turns 4-way STS conflicts into 2-way.
#define ESWZ(v) (4 * (((v) >> 2) & 7))

// ---------------------------------------------------------------------------
// Kernel 1: codeword norms (sequential mul+add, v ascending) + zero histogram
// ---------------------------------------------------------------------------
__global__ void vq_prep_kernel(const float* __restrict__ emb) {
    int k = blockIdx.x * blockDim.x + threadIdx.x;   // 0..1023
    if (k < KCW) {
        float acc = 0.0f;
        const float* e = emb + (size_t)k * VDIM;
        #pragma unroll 8
        for (int v = 0; v < VDIM; v++)
            acc = __fadd_rn(acc, __fmul_rn(e[v], e[v]));
        g_en[k]     = acc;
        g_counts[k] = 0;
    }
}

// ---------------------------------------------------------------------------
// Kernel 2: fused GEMM + argmin + histogram + outputs
// grid 1024 (64 samples each), 256 threads, 1 CTA/SM (smem-pinned)
// thread tile: 4 rows x 16 codewords (8 packed pairs)
// ---------------------------------------------------------------------------
__global__ __launch_bounds__(256, 1)
void vq_main_kernel(const float* __restrict__ x, const float* __restrict__ emb,
                    float* __restrict__ out0, float* __restrict__ out1,
                    float* __restrict__ out2) {
    extern __shared__ float sm[];
    float* xs2  = sm;                          // [VDIM][XST] duplicated x pairs
    float* es   = sm + XS_FLOATS;              // [VDIM][EST] e chunk (transposed, swizzled)
    float* en_s = sm + XS_FLOATS + ES_FLOATS;  // [KCW] codeword norms
    float* xn_s = en_s + KCW;                  // [BM] row norms
    // post-loop overlays on es:
    float* red_val = es;                       // [16][66]
    int*   red_idx = (int*)(es + 1056);        // [16][66]
    int*   amin_s  = (int*)(es + 2112);        // [BM]
    float* rowsum  = es + 2176;                // [BM]

    const int tid  = threadIdx.x;
    const int tx   = tid & 15;                 // 16 codeword-pair groups
    const int ty   = tid >> 4;                 // 16 row groups
    const int row0 = blockIdx.x * BM;

    // ---- load x tile (coalesced float4), store duplicated pairs (v-major) ----
    const float4* x4 = reinterpret_cast<const float4*>(x) + (size_t)row0 * (VDIM / 4);
    #pragma unroll
    for (int t = 0; t < 4; t++) {
        int lin4 = tid + t * 256;              // 1024 float4
        int r    = lin4 >> 4;
        int v4   = lin4 & 15;
        float4 val = x4[lin4];
        *reinterpret_cast<float2*>(xs2 + (v4 * 4 + 0) * XST + 2 * r) = make_float2(val.x, val.x);
        *reinterpret_cast<float2*>(xs2 + (v4 * 4 + 1) * XST + 2 * r) = make_float2(val.y, val.y);
        *reinterpret_cast<float2*>(xs2 + (v4 * 4 + 2) * XST + 2 * r) = make_float2(val.z, val.z);
        *reinterpret_cast<float2*>(xs2 + (v4 * 4 + 3) * XST + 2 * r) = make_float2(val.w, val.w);
    }
    // ---- copy codeword norms into smem (4 per thread) ----
    #pragma unroll
    for (int t = 0; t < 4; t++) en_s[tid + t * 256] = g_en[tid + t * 256];
    __syncthreads();

    // ---- row norms ||x_r||^2 (sequential mul+add, v ascending) ----
    if (tid < BM) {
        float acc = 0.0f;
        const float* xr = xs2 + 2 * tid;
        #pragma unroll 8
        for (int v = 0; v < VDIM; v++) {
            float xv = xr[v * XST];
            acc = __fadd_rn(acc, __fmul_rn(xv, xv));
        }
        xn_s[tid] = acc;
    }

    float minv[4];
    int   mini[4];
    #pragma unroll
    for (int i = 0; i < 4; i++) { minv[i] = 3.402823466e38f; mini[i] = 0; }

    const ull NEG2 = 0xC0000000C0000000ULL;    // {-2.0f, -2.0f}

    // thread covers rows r_i = ty + 16*i (i<4), codewords k = c*256 + 32*m + 2*tx + {0,1} (m<8)
    for (int c = 0; c < NCHUNK; c++) {
        if (c > 0) __syncthreads();            // compute done before overwriting es
        const float4* e4 = reinterpret_cast<const float4*>(emb) + (size_t)c * (BK * VDIM / 4);
        #pragma unroll
        for (int t = 0; t < 16; t++) {
            int lin4 = tid + t * 256;          // 4096 float4
            int k    = lin4 >> 4;
            int v4   = lin4 & 15;
            float4 val = e4[lin4];
            int swz = 4 * (v4 & 7);            // ESWZ(4*v4+j) == ESWZ(4*v4)
            es[(((v4 * 4 + 0) * EST + k)) ^ swz] = val.x;
            es[(((v4 * 4 + 1) * EST + k)) ^ swz] = val.y;
            es[(((v4 * 4 + 2) * EST + k)) ^ swz] = val.z;
            es[(((v4 * 4 + 3) * EST + k)) ^ swz] = val.w;
        }
        __syncthreads();

        ull acc[4][8];
        #pragma unroll
        for (int i = 0; i < 4; i++)
            #pragma unroll
            for (int m = 0; m < 8; m++) acc[i][m] = 0ULL;

        const int txk = 2 * tx;
        const int tyk = 2 * ty;
        // sequential FMA over v=0..63, single accumulator per (row, codeword)
        #pragma unroll 8
        for (int v = 0; v < VDIM; v++) {
            int ei = (v * EST + txk) ^ ESWZ(v);
            ull ep[8];
            #pragma unroll
            for (int m = 0; m < 8; m++)
                ep[m] = *reinterpret_cast<const ull*>(es + ei + 32 * m);
            ull xp[4];
            #pragma unroll
            for (int i = 0; i < 4; i++)
                xp[i] = *reinterpret_cast<const ull*>(xs2 + v * XST + tyk + 32 * i);
            #pragma unroll
            for (int i = 0; i < 4; i++)
                #pragma unroll
                for (int m = 0; m < 8; m++)
                    acc[i][m] = ffma2(xp[i], ep[m], acc[i][m]);
        }

        // score = fl( fl( xn - fl(2*dot) ) + en ) via packed ops (exact per lane)
        ull xn2[4];
        #pragma unroll
        for (int i = 0; i < 4; i++) {
            float xnv = xn_s[ty + 16 * i];
            xn2[i] = pack2(xnv, xnv);
        }
        #pragma unroll
        for (int m = 0; m < 8; m++) {
            int kk = 32 * m + txk;             // local codeword pair base
            int k0 = c * BK + kk;              // global
            ull en2 = *reinterpret_cast<const ull*>(en_s + k0);
            #pragma unroll
            for (int i = 0; i < 4; i++) {
                ull s2 = fadd2(fadd2(xn2[i], fmul2(acc[i][m], NEG2)), en2);
                float s0, s1;
                unpack2(s2, s0, s1);
                if (s0 < minv[i]) { minv[i] = s0; mini[i] = k0; }
                if (s1 < minv[i]) { minv[i] = s1; mini[i] = k0 + 1; }
            }
        }
    }

    // ---- cross-thread argmin reduction (16 candidates per row) ----
    __syncthreads();
    #pragma unroll
    for (int i = 0; i < 4; i++) {
        int r = ty + 16 * i;
        red_val[tx * 66 + r] = minv[i];
        red_idx[tx * 66 + r] = mini[i];
    }
    __syncthreads();
    if (tid < BM) {
        int r = tid;
        float bv = red_val[r];
        int   bi = red_idx[r];
        #pragma unroll
        for (int j = 1; j < 16; j++) {
            float v  = red_val[j * 66 + r];
            int   id = red_idx[j * 66 + r];
            if (v < bv || (v == bv && id < bi)) { bv = v; bi = id; }
        }
        amin_s[r] = bi;
        rowsum[r] = 0.0f;
        atomicAdd(&g_counts[bi], 1);
    }
    __syncthreads();

    // ---- outputs: out0 = fl(fl(o - x) + x), out1 = out2 = sum_v (x-o)^2 ----
    #pragma unroll 4
    for (int t = 0; t < 16; t++) {
        int i = t * 256 + tid;                 // 4096 elements
        int r = i >> 6;
        int v = i & 63;
        float o  = emb[amin_s[r] * VDIM + v];
        float xv = xs2[v * XST + 2 * r];
        float d  = __fsub_rn(xv, o);
        float sq = __fmul_rn(d, d);
        #pragma unroll
        for (int off = 16; off > 0; off >>= 1)
            sq += __shfl_down_sync(0xffffffffu, sq, off);
        if ((tid & 31) == 0) atomicAdd(&rowsum[r], sq);   // 2 adds/row: order-invariant
        out0[(size_t)(row0 + r) * VDIM + v] = __fadd_rn(__fsub_rn(o, xv), xv);
    }
    __syncthreads();
    if (tid < BM) {
        float s = rowsum[tid];
        out1[row0 + tid] = s;
        out2[row0 + tid] = s;
    }
}

// ---------------------------------------------------------------------------
// Kernel 3: entropy of the histogram
// ---------------------------------------------------------------------------
__global__ void vq_entropy_kernel(float* __restrict__ ent) {
    __shared__ float warpsum[32];
    int k = threadIdx.x;                   // 1024 threads
    int c = g_counts[k];
    float term = 0.0f;
    if (c > 0) {
        float p = (float)c * (1.0f / 65536.0f);
        term = -p * logf(p);
    }
    #pragma unroll
    for (int off = 16; off > 0; off >>= 1)
        term += __shfl_down_sync(0xffffffffu, term, off);
    int lane = k & 31, wid = k >> 5;
    if (lane == 0) warpsum[wid] = term;
    __syncthreads();
    if (wid == 0) {
        float s = warpsum[lane];
        #pragma unroll
        for (int off = 16; off > 0; off >>= 1)
            s += __shfl_down_sync(0xffffffffu, s, off);
        if (lane == 0) *ent = s;
    }
}

// ---------------------------------------------------------------------------
extern "C" void kernel_launch(void* const* d_in, const int* in_sizes, int n_in,
                              void* d_out, int out_size) {
    const float* x;
    const float* emb;
    if (in_sizes[0] == NS_TOTAL * VDIM) {
        x   = (const float*)d_in[0];
        emb = (const float*)d_in[1];
    } else {
        x   = (const float*)d_in[1];
        emb = (const float*)d_in[0];
    }

    float* out0 = (float*)d_out;                        // 65536*64
    float* out1 = out0 + (size_t)NS_TOTAL * VDIM;       // 65536
    float* out2 = out1 + NS_TOTAL;                      // 65536
    float* ent  = out2 + NS_TOTAL;                      // 1

    cudaFuncSetAttribute(vq_main_kernel,
                         cudaFuncAttributeMaxDynamicSharedMemorySize, SMEM_BYTES);

    vq_prep_kernel<<<4, 256>>>(emb);
    vq_main_kernel<<<1024, 256, SMEM_BYTES>>>(x, emb, out0, out1, out2);
    vq_entropy_kernel<<<1, 1024>>>(ent);
}